// round 2
// baseline (speedup 1.0000x reference)
#include <cuda_runtime.h>

// Problem constants
#define HIMG 48
#define KSZ  5
#define OH   44                 // 48 - 5 + 1
#define PNUM 1936               // 44*44
#define CIN  3
#define KN   16
#define BATCH 2
#define IMG_ELEMS (CIN*HIMG*HIMG)        // 6912 floats = 27.6 KB
#define MU_OUT_ELEMS (BATCH*KN*OH*OH)    // 61952
#define TILES_PER_ROW 11                 // 44/4
#define NTILE 484                        // 11*44 (4-wide tiles, same row)

// ---------------------------------------------------------------------------
// sigma kernel: sigma[b,kn,p,q] = softplus(w_sigma[kn]) * dot(patch_p, patch_q)
// Block = (one p-tile of 4 consecutive px, one batch). 128 threads, each
// thread owns 4x4 (p,q) dot tiles; whole image lives in smem.
// ---------------------------------------------------------------------------
__global__ __launch_bounds__(128)
void vdp_sigma_kernel(const float* __restrict__ mu_in,
                      const float* __restrict__ w_sigma,
                      float* __restrict__ out)
{
    __shared__ float img[IMG_ELEMS];
    __shared__ float sp[KN];

    const int b   = blockIdx.y;
    const int tp  = blockIdx.x;          // p-tile index, 0..483
    const int tid = threadIdx.x;

    // Cooperative image load (float4, fully aligned: 6912 % 4 == 0)
    {
        const float4* src = reinterpret_cast<const float4*>(mu_in + b * IMG_ELEMS);
        float4* dst = reinterpret_cast<float4*>(img);
        #pragma unroll
        for (int i = tid; i < IMG_ELEMS / 4; i += 128) dst[i] = src[i];
    }
    if (tid < KN) sp[tid] = log1pf(expf(w_sigma[tid]));
    __syncthreads();

    const int py  = tp / TILES_PER_ROW;
    const int px0 = (tp % TILES_PER_ROW) * 4;

    float* __restrict__ sig = out + MU_OUT_ELEMS + (long)b * KN * (long)PNUM * PNUM;

    for (int tq = tid; tq < NTILE; tq += 128) {
        const int qy  = tq / TILES_PER_ROW;
        const int qx0 = (tq % TILES_PER_ROW) * 4;

        float acc[4][4];
        #pragma unroll
        for (int pp = 0; pp < 4; pp++)
            #pragma unroll
            for (int qq = 0; qq < 4; qq++) acc[pp][qq] = 0.0f;

        #pragma unroll
        for (int c = 0; c < CIN; c++) {
            #pragma unroll
            for (int i = 0; i < KSZ; i++) {
                // p-side row segment: same address for all lanes -> smem broadcast
                const float* prow = img + c * (HIMG * HIMG) + (py + i) * HIMG + px0;
                // q-side row segment: consecutive lanes -> conflict-free LDS.128
                const float* qrow = img + c * (HIMG * HIMG) + (qy + i) * HIMG + qx0;

                float a[8], bq[8];
                float4 t0 = *reinterpret_cast<const float4*>(prow);
                float4 t1 = *reinterpret_cast<const float4*>(prow + 4);
                a[0]=t0.x; a[1]=t0.y; a[2]=t0.z; a[3]=t0.w;
                a[4]=t1.x; a[5]=t1.y; a[6]=t1.z; a[7]=t1.w;
                float4 u0 = *reinterpret_cast<const float4*>(qrow);
                float4 u1 = *reinterpret_cast<const float4*>(qrow + 4);
                bq[0]=u0.x; bq[1]=u0.y; bq[2]=u0.z; bq[3]=u0.w;
                bq[4]=u1.x; bq[5]=u1.y; bq[6]=u1.z; bq[7]=u1.w;

                #pragma unroll
                for (int j = 0; j < KSZ; j++)
                    #pragma unroll
                    for (int pp = 0; pp < 4; pp++)
                        #pragma unroll
                        for (int qq = 0; qq < 4; qq++)
                            acc[pp][qq] += a[pp + j] * bq[qq + j];
            }
        }

        // Write 16 kn * 4 p-rows * float4(q) = 1 KB per thread-tile.
        // For fixed (kn,pp): lanes write 16B apart -> 512B contiguous per warp.
        const int p0 = py * OH + px0;
        const int q0 = qy * OH + qx0;
        #pragma unroll
        for (int kn = 0; kn < KN; kn++) {
            const float s = sp[kn];
            #pragma unroll
            for (int pp = 0; pp < 4; pp++) {
                float4 v;
                v.x = acc[pp][0] * s;
                v.y = acc[pp][1] * s;
                v.z = acc[pp][2] * s;
                v.w = acc[pp][3] * s;
                *reinterpret_cast<float4*>(
                    sig + ((long)kn * PNUM + (p0 + pp)) * (long)PNUM + q0) = v;
            }
        }
    }
}

// ---------------------------------------------------------------------------
// mu kernel: plain VALID cross-correlation, mu_out[b,kn,y,x]
// One block per (b,kn); image + this kn's 75 weights in smem.
// ---------------------------------------------------------------------------
__global__ __launch_bounds__(256)
void vdp_mu_kernel(const float* __restrict__ mu_in,
                   const float* __restrict__ w_mu,
                   float* __restrict__ out)
{
    __shared__ float img[IMG_ELEMS];
    __shared__ float w[CIN * KSZ * KSZ];

    const int kn = blockIdx.x;
    const int b  = blockIdx.y;
    const int tid = threadIdx.x;

    {
        const float4* src = reinterpret_cast<const float4*>(mu_in + b * IMG_ELEMS);
        float4* dst = reinterpret_cast<float4*>(img);
        for (int i = tid; i < IMG_ELEMS / 4; i += 256) dst[i] = src[i];
    }
    if (tid < CIN * KSZ * KSZ) w[tid] = w_mu[kn * (CIN * KSZ * KSZ) + tid];
    __syncthreads();

    float* __restrict__ dst = out + ((long)b * KN + kn) * (OH * OH);

    for (int o = tid; o < OH * OH; o += 256) {
        const int y = o / OH;
        const int x = o % OH;
        float s = 0.0f;
        #pragma unroll
        for (int c = 0; c < CIN; c++)
            #pragma unroll
            for (int i = 0; i < KSZ; i++)
                #pragma unroll
                for (int j = 0; j < KSZ; j++)
                    s += img[c * (HIMG * HIMG) + (y + i) * HIMG + (x + j)]
                       * w[c * (KSZ * KSZ) + i * KSZ + j];
        dst[o] = s;
    }
}

// ---------------------------------------------------------------------------
extern "C" void kernel_launch(void* const* d_in, const int* in_sizes, int n_in,
                              void* d_out, int out_size)
{
    const float* mu_in   = (const float*)d_in[0];  // [2,3,48,48]
    const float* w_mu    = (const float*)d_in[1];  // [16,3,5,5]
    const float* w_sigma = (const float*)d_in[2];  // [16]
    float* out = (float*)d_out;                    // mu_out (61952) ++ sigma (119939072)

    (void)in_sizes; (void)n_in; (void)out_size;

    // mu path: 32 small blocks
    {
        dim3 grid(KN, BATCH);
        vdp_mu_kernel<<<grid, 256>>>(mu_in, w_mu, out);
    }
    // sigma path: 968 blocks, write-bound
    {
        dim3 grid(NTILE, BATCH);
        vdp_sigma_kernel<<<grid, 128>>>(mu_in, w_sigma, out);
    }
}

// round 7
// speedup vs baseline: 1.1410x; 1.1410x over previous
#include <cuda_runtime.h>

// Problem constants
#define HIMG 48
#define KSZ  5
#define OH   44                 // 48 - 5 + 1
#define PNUM 1936               // 44*44
#define CIN  3
#define KN   16
#define BATCH 2
#define IMG_ELEMS (CIN*HIMG*HIMG)        // 6912 floats = 27.6 KB
#define MU_OUT_ELEMS (BATCH*KN*OH*OH)    // 61952
#define TILES_PER_ROW 11                 // 44/4
#define NTILE 484                        // 11*44 (4-wide q/p tiles)
#define QSPLIT 2
#define QT_PER (NTILE/QSPLIT)            // 242 q-tiles per block

// ---------------------------------------------------------------------------
// Fused kernel.
//   blocks with blockIdx.x <  NTILE : sigma path (one p-tile, half the q-tiles)
//   blocks with blockIdx.x >= NTILE : mu path (one (b,kn) plain conv)
// sigma[b,kn,p,q] = softplus(w_sigma[kn]) * dot(patch_p, patch_q)
// ---------------------------------------------------------------------------
__global__ __launch_bounds__(128, 5)
void vdp_fused_kernel(const float* __restrict__ mu_in,
                      const float* __restrict__ w_mu,
                      const float* __restrict__ w_sigma,
                      float* __restrict__ out)
{
    __shared__ float img[IMG_ELEMS];
    __shared__ float sp[KN];
    __shared__ float w[CIN * KSZ * KSZ];

    const int b   = blockIdx.z;
    const int bx  = blockIdx.x;
    const int tid = threadIdx.x;

    // Cooperative image load (float4, aligned: 6912 % 4 == 0)
    {
        const float4* src = reinterpret_cast<const float4*>(mu_in + b * IMG_ELEMS);
        float4* dst = reinterpret_cast<float4*>(img);
        #pragma unroll
        for (int i = tid; i < IMG_ELEMS / 4; i += 128) dst[i] = src[i];
    }

    // ------------------------------ mu path ------------------------------
    if (bx >= NTILE) {
        const int kn = (bx - NTILE) * QSPLIT + blockIdx.y;   // 0..15
        if (tid < CIN * KSZ * KSZ) w[tid] = w_mu[kn * (CIN * KSZ * KSZ) + tid];
        __syncthreads();

        float* __restrict__ dst = out + ((long)b * KN + kn) * (OH * OH);
        for (int o = tid; o < OH * OH; o += 128) {
            const int y = o / OH;
            const int x = o % OH;
            float s = 0.0f;
            #pragma unroll
            for (int c = 0; c < CIN; c++)
                #pragma unroll
                for (int i = 0; i < KSZ; i++)
                    #pragma unroll
                    for (int j = 0; j < KSZ; j++)
                        s += img[c * (HIMG * HIMG) + (y + i) * HIMG + (x + j)]
                           * w[c * (KSZ * KSZ) + i * KSZ + j];
            dst[o] = s;
        }
        return;
    }

    // ----------------------------- sigma path ----------------------------
    if (tid < KN) sp[tid] = log1pf(expf(w_sigma[tid]));
    __syncthreads();

    const int py  = bx / TILES_PER_ROW;
    const int px0 = (bx % TILES_PER_ROW) * 4;

    float* __restrict__ sig = out + MU_OUT_ELEMS + (long)b * KN * (long)PNUM * PNUM;
    const long knStride = (long)PNUM * PNUM;

    const int qlo = blockIdx.y * QT_PER;

    for (int tq = qlo + tid; tq < qlo + QT_PER; tq += 128) {
        const int qy  = tq / TILES_PER_ROW;
        const int qx0 = (tq % TILES_PER_ROW) * 4;

        float acc[4][4];
        #pragma unroll
        for (int pp = 0; pp < 4; pp++)
            #pragma unroll
            for (int qq = 0; qq < 4; qq++) acc[pp][qq] = 0.0f;

        #pragma unroll
        for (int c = 0; c < CIN; c++) {
            #pragma unroll
            for (int i = 0; i < KSZ; i++) {
                // p-side: same address for all lanes -> smem broadcast
                const float* prow = img + c * (HIMG * HIMG) + (py + i) * HIMG + px0;
                // q-side: consecutive lanes -> conflict-free LDS.128
                const float* qrow = img + c * (HIMG * HIMG) + (qy + i) * HIMG + qx0;

                float a[8], bq[8];
                float4 t0 = *reinterpret_cast<const float4*>(prow);
                float4 t1 = *reinterpret_cast<const float4*>(prow + 4);
                a[0]=t0.x; a[1]=t0.y; a[2]=t0.z; a[3]=t0.w;
                a[4]=t1.x; a[5]=t1.y; a[6]=t1.z; a[7]=t1.w;
                float4 u0 = *reinterpret_cast<const float4*>(qrow);
                float4 u1 = *reinterpret_cast<const float4*>(qrow + 4);
                bq[0]=u0.x; bq[1]=u0.y; bq[2]=u0.z; bq[3]=u0.w;
                bq[4]=u1.x; bq[5]=u1.y; bq[6]=u1.z; bq[7]=u1.w;

                #pragma unroll
                for (int j = 0; j < KSZ; j++)
                    #pragma unroll
                    for (int pp = 0; pp < 4; pp++)
                        #pragma unroll
                        for (int qq = 0; qq < 4; qq++)
                            acc[pp][qq] += a[pp + j] * bq[qq + j];
            }
        }

        // Store: 16 kn * 4 p-rows * float4(q). kn loop NOT unrolled to keep
        // live-address count (and register pressure) low; running pointer.
        const int p0 = py * OH + px0;
        const int q0 = qy * OH + qx0;
        float* ptr = sig + (long)p0 * PNUM + q0;
        #pragma unroll 1
        for (int kn = 0; kn < KN; kn++) {
            const float s = sp[kn];
            #pragma unroll
            for (int pp = 0; pp < 4; pp++) {
                float4 v;
                v.x = acc[pp][0] * s;
                v.y = acc[pp][1] * s;
                v.z = acc[pp][2] * s;
                v.w = acc[pp][3] * s;
                *reinterpret_cast<float4*>(ptr + pp * PNUM) = v;
            }
            ptr += knStride;
        }
    }
}

// ---------------------------------------------------------------------------
extern "C" void kernel_launch(void* const* d_in, const int* in_sizes, int n_in,
                              void* d_out, int out_size)
{
    const float* mu_in   = (const float*)d_in[0];  // [2,3,48,48]
    const float* w_mu    = (const float*)d_in[1];  // [16,3,5,5]
    const float* w_sigma = (const float*)d_in[2];  // [16]
    float* out = (float*)d_out;                    // mu_out (61952) ++ sigma (119939072)

    (void)in_sizes; (void)n_in; (void)out_size;

    // 484 sigma-x blocks + 8 mu-x blocks; y = q-split (or kn lsb for mu); z = batch
    dim3 grid(NTILE + KN / QSPLIT, QSPLIT, BATCH);
    vdp_fused_kernel<<<grid, 128>>>(mu_in, w_mu, w_sigma, out);
}